// round 13
// baseline (speedup 1.0000x reference)
#include <cuda_runtime.h>
#include <cuda_bf16.h>
#include <cstdint>

#define NBATCH 8
#define CDIM   256
#define TDIM   16384
#define DCODES 512
#define BT     64
#define NTHREADS 256
#define MARGIN 0.25f

// ---- smem byte layout ----
// Ah: 4 kchunks x [64 t x 128 B], XOR-swizzled, 32 KB @0
#define AK        8192
#define OFF_HN    32768                 // float[512]
#define OFF_FIDX  34816                 // int[64]
#define OFF_BQ    35072                 // float[64]
#define OFF_FLAGS 35328                 // int[64]
#define OFF_FLAGN 35584                 // int
#define SMEM_BYTES 35600
// overlays in Ah region (dead post-mainloop): pb[64][16] u32 @0, ps@4096;
// epilogue rowsT swizzled needs 64KB -> does NOT fit; use 2 halves of 32KB.

__device__ float g_hnorm[DCODES];
// B in mma-fragment order: [dblock 64][kblock 16][lane 32] x 8B
__device__ __align__(256) uint2 g_bfrag[64 * 16 * 32];

// ---------------- helpers ----------------
__device__ __forceinline__ uint32_t smem_u32(const void* p) {
    uint32_t a;
    asm("{ .reg .u64 t; cvta.to.shared.u64 t, %1; cvt.u32.u64 %0, t; }" : "=r"(a) : "l"(p));
    return a;
}
__device__ __forceinline__ void ldmx4(uint32_t r[4], uint32_t addr) {
    asm volatile("ldmatrix.sync.aligned.m8n8.x4.shared.b16 {%0,%1,%2,%3}, [%4];"
                 : "=r"(r[0]), "=r"(r[1]), "=r"(r[2]), "=r"(r[3]) : "r"(addr));
}
__device__ __forceinline__ void mma16816(float c[4], const uint32_t a[4], uint2 b) {
    asm volatile("mma.sync.aligned.m16n8k16.row.col.f32.bf16.bf16.f32 "
                 "{%0,%1,%2,%3}, {%4,%5,%6,%7}, {%8,%9}, {%0,%1,%2,%3};"
                 : "+f"(c[0]), "+f"(c[1]), "+f"(c[2]), "+f"(c[3])
                 : "r"(a[0]), "r"(a[1]), "r"(a[2]), "r"(a[3]), "r"(b.x), "r"(b.y));
}

// order-preserving (score, idx) pack: larger packed = better score, tie -> smaller idx
__device__ __forceinline__ uint32_t pack_si(float v, int d) {
    uint32_t b = __float_as_uint(v);
    b ^= ((int32_t)b < 0) ? 0xFFFFFFFFu : 0x80000000u;
    return (b & ~511u) | (uint32_t)(511 - d);
}
__device__ __forceinline__ float unpack_s(uint32_t p) {
    uint32_t u = p & ~511u;
    uint32_t b = (u & 0x80000000u) ? (u ^ 0x80000000u) : ~u;
    return __uint_as_float(b);
}
__device__ __forceinline__ int unpack_i(uint32_t p) { return 511 - (int)(p & 511u); }

// swizzled rowsT offset (bytes), 64-t rows, 32KB half (128 c)
__device__ __forceinline__ uint32_t rt_off(int c, int t) {
    return (uint32_t)(c * 256 + ((((t >> 2) ^ (c & 15)) << 4) | ((t & 3) << 2)));
}

// ---------------- prologue 1: hnorm ----------------
__global__ void vq_hnorm_kernel(const float* __restrict__ dict) {
    const int wid = threadIdx.x >> 5, lane = threadIdx.x & 31;
    const int d = blockIdx.x * 8 + wid;
    const float4* row = reinterpret_cast<const float4*>(dict + (size_t)d * CDIM);
    float4 a = row[lane * 2];
    float4 b = row[lane * 2 + 1];
    float s = a.x * a.x + a.y * a.y + a.z * a.z + a.w * a.w
            + b.x * b.x + b.y * b.y + b.z * b.z + b.w * b.w;
#pragma unroll
    for (int o = 16; o; o >>= 1) s += __shfl_xor_sync(0xffffffffu, s, o);
    if (lane == 0) g_hnorm[d] = 0.5f * s;
}

// ---------------- prologue 2: dict -> bf16 mma-fragment order ----------------
// For m16n8k16 B-fragment: lane l of (db, kb) holds
//   {B[d][c0], B[d][c0+1]} and {B[d][c0+8], B[d][c0+9]}
// with d = db*8 + l/4, c0 = kb*16 + (l&3)*2.
__global__ void vq_bfrag_kernel(const float* __restrict__ dict) {
    const int db = blockIdx.x;                    // 0..63
    const int kb = threadIdx.x >> 5;              // 0..15
    const int lane = threadIdx.x & 31;
    const int d  = db * 8 + (lane >> 2);
    const int c0 = kb * 16 + (lane & 3) * 2;
    const float* row = dict + (size_t)d * CDIM;
    __nv_bfloat162 lo = __float22bfloat162_rn(make_float2(row[c0],     row[c0 + 1]));
    __nv_bfloat162 hi = __float22bfloat162_rn(make_float2(row[c0 + 8], row[c0 + 9]));
    uint2 v;
    v.x = *reinterpret_cast<uint32_t*>(&lo);
    v.y = *reinterpret_cast<uint32_t*>(&hi);
    g_bfrag[(db * 16 + kb) * 32 + lane] = v;
}

// ---------------- main kernel ----------------
__global__ __launch_bounds__(NTHREADS, 3)
void vq_main_kernel(const float* __restrict__ inputs,
                    const float* __restrict__ dict,
                    float* __restrict__ out) {
    extern __shared__ float smem[];
    const uint32_t sbase = smem_u32(smem);
    char* smc = reinterpret_cast<char*>(smem);
    float* shn   = reinterpret_cast<float*>(smc + OFF_HN);
    int*   fidx  = reinterpret_cast<int*>(smc + OFF_FIDX);
    float* bq    = reinterpret_cast<float*>(smc + OFF_BQ);
    int*   flags = reinterpret_cast<int*>(smc + OFF_FLAGS);
    int*   flagn = reinterpret_cast<int*>(smc + OFF_FLAGN);

    const int tid = threadIdx.x;
    const int wid = tid >> 5, lane = tid & 31;
    const int wm = wid >> 2, wn = wid & 3;           // 2 x 4 warp grid (m32 x n32)
    const int n = blockIdx.x >> 8, tt0 = (blockIdx.x & 255) << 6;
    const size_t E = (size_t)NBATCH * CDIM * TDIM;

    if (tid == 0) *flagn = 0;
    shn[tid] = g_hnorm[tid];
    shn[tid + 256] = g_hnorm[tid + 256];

    // ===== A build: direct LDG -> bf16 -> swizzled STS.128 (conflict-free) =====
    {
        const int t = tid & 63;
        const int rep = tid >> 6;                     // 0..3 == kchunk
        const float* xcol = inputs + (size_t)n * CDIM * TDIM + tt0 + t;
        const int x7 = t & 7;
#pragma unroll 2
        for (int q = 0; q < 8; q++) {
            const int c0 = rep * 64 + q * 8;
            float xv[8];
#pragma unroll
            for (int j = 0; j < 8; j++)
                xv[j] = xcol[(size_t)(c0 + j) * TDIM];
            __nv_bfloat162 h;
            uint4 v;
            h = __float22bfloat162_rn(make_float2(xv[0], xv[1])); v.x = *reinterpret_cast<uint32_t*>(&h);
            h = __float22bfloat162_rn(make_float2(xv[2], xv[3])); v.y = *reinterpret_cast<uint32_t*>(&h);
            h = __float22bfloat162_rn(make_float2(xv[4], xv[5])); v.z = *reinterpret_cast<uint32_t*>(&h);
            h = __float22bfloat162_rn(make_float2(xv[6], xv[7])); v.w = *reinterpret_cast<uint32_t*>(&h);
            *reinterpret_cast<uint4*>(smc + rep * AK + t * 128 + ((q ^ x7) << 4)) = v;
        }
    }
    __syncthreads();

    // ===== barrier-free mainloop: B fragments via coalesced LDG.64 from L2 =====
    uint32_t b2[4], s2[4];                            // packed (score, idx) top-2
#pragma unroll
    for (int i = 0; i < 4; i++) { b2[i] = 0u; s2[i] = 0u; }

    const uint32_t aBase = sbase + (uint32_t)(wm * 4096 + (lane & 15) * 128);
    uint32_t aOff[4];
#pragma unroll
    for (int ks = 0; ks < 4; ks++)
        aOff[ks] = (uint32_t)(((ks * 2 + (lane >> 4)) ^ (lane & 7)) << 4);

    // warp's B fragment base: db = dg*16 + wn*4 + nt
    const uint2* bfr = g_bfrag + (size_t)(wn * 4) * 16 * 32 + lane;

    for (int dg = 0; dg < 4; dg++) {
        float acc[2][4][4];
#pragma unroll
        for (int mt = 0; mt < 2; mt++)
#pragma unroll
            for (int nt = 0; nt < 4; nt++)
#pragma unroll
                for (int e = 0; e < 4; e++) acc[mt][nt][e] = 0.f;

        const uint2* bdg = bfr + (size_t)(dg * 16) * 16 * 32;

#pragma unroll 4
        for (int kb = 0; kb < 16; kb++) {
            const int kc = kb >> 2, ks = kb & 3;
            uint2 bf[4];
#pragma unroll
            for (int nt = 0; nt < 4; nt++)
                bf[nt] = bdg[((size_t)nt * 16 + kb) * 32];
            uint32_t ah[2][4];
            const uint32_t aH = aBase + kc * AK + aOff[ks];
            ldmx4(ah[0], aH);
            ldmx4(ah[1], aH + 2048);
#pragma unroll
            for (int mt = 0; mt < 2; mt++)
#pragma unroll
                for (int nt = 0; nt < 4; nt++) mma16816(acc[mt][nt], ah[mt], bf[nt]);
        }

        const int dbase = dg * 128 + wn * 32 + (lane & 3) * 2;
#pragma unroll
        for (int mt = 0; mt < 2; mt++) {
#pragma unroll
            for (int rh = 0; rh < 2; rh++) {
                const int li = mt * 2 + rh;
                uint32_t b_ = b2[li], s_ = s2[li];
#pragma unroll
                for (int nt = 0; nt < 4; nt++) {
#pragma unroll
                    for (int cc = 0; cc < 2; cc++) {
                        const int d = dbase + nt * 8 + cc;
                        float v = acc[mt][nt][rh * 2 + cc] - shn[d];
                        uint32_t p = pack_si(v, d);
                        if (p > b_) { s_ = b_; b_ = p; }
                        else if (p > s_) s_ = p;
                    }
                }
                b2[li] = b_; s2[li] = s_;
            }
        }
    }
    __syncthreads();   // Ah dead; overlay tables

    // ================= per-group top-2 publish (packed) =================
    uint32_t* pb = reinterpret_cast<uint32_t*>(smem);      // [64][16]
    uint32_t* ps = pb + 1024;                              // [64][16]
    {
        const int slot = wn * 4 + (lane & 3);
#pragma unroll
        for (int mt = 0; mt < 2; mt++)
#pragma unroll
            for (int rh = 0; rh < 2; rh++) {
                const int li = mt * 2 + rh;
                const int t = wm * 32 + mt * 16 + (lane >> 2) + rh * 8;
                pb[t * 16 + slot] = b2[li];
                ps[t * 16 + slot] = s2[li];
            }
    }
    __syncthreads();

    // ================= approx argmax + candidate flagging =================
    if (tid < BT) {
        uint32_t B = 0u;
#pragma unroll 4
        for (int q = 0; q < 16; q++) B = max(B, pb[tid * 16 + q]);
        const int I = unpack_i(B);
        const float Bf = unpack_s(B);
        int ncand = 0;
#pragma unroll 4
        for (int k = 0; k < 32; k++) {
            uint32_t p = (k < 16) ? pb[tid * 16 + k] : ps[tid * 16 + (k - 16)];
            if (unpack_s(p) > Bf - MARGIN && unpack_i(p) != I) ncand++;
        }
        fidx[tid] = I; bq[tid] = Bf;
        if (ncand) { int p = atomicAdd(flagn, 1); flags[p] = tid; }
    }
    __syncthreads();

    // ================= exact fp32 rescore of ALL in-margin candidates =================
    {
        const int nf = *flagn;
        for (int e = wid; e < nf; e += 8) {
            const int q = flags[e];
            const float B = bq[q];
            const float* xp = inputs + ((size_t)n * CDIM) * TDIM + tt0 + q;
            float xr[8];
#pragma unroll
            for (int j = 0; j < 8; j++) xr[j] = xp[(size_t)(lane + 32 * j) * TDIM];
            float bestE = -3.0e38f; int bestI = 0x3fffffff;
            for (int k = 0; k < 32; k++) {
                uint32_t pk = (k < 16) ? pb[q * 16 + k] : ps[q * 16 + (k - 16)];
                if (unpack_s(pk) > B - MARGIN) {
                    const int i2 = unpack_i(pk);
                    const float* drow = dict + (size_t)i2 * CDIM;
                    float p = 0.f;
#pragma unroll
                    for (int j = 0; j < 8; j++) p += xr[j] * drow[lane + 32 * j];
#pragma unroll
                    for (int o = 16; o; o >>= 1) p += __shfl_xor_sync(0xffffffffu, p, o);
                    float c = p - shn[i2];
                    if (c > bestE || (c == bestE && i2 < bestI)) { bestE = c; bestI = i2; }
                }
            }
            if (lane == 0) fidx[q] = bestI;
        }
    }
    __syncthreads();

    if (tid < BT)
        out[2 * E + (size_t)n * TDIM + tt0 + tid] = (float)fidx[tid];

    // ================= swizzled conflict-free epilogue: 2 c-halves of 128 =================
    {
        float* out_e = out;
        float* out_p = out + E;
        for (int h = 0; h < 2; h++) {
            __syncthreads();
            // gather: warp owns t-groups g = wid + 8*g4 (4 t each); 16 groups
#pragma unroll
            for (int g4 = 0; g4 < 2; g4++) {
                const int g = wid + 8 * g4;
                const float* r0 = dict + (size_t)fidx[4 * g    ] * CDIM + h * 128;
                const float* r1 = dict + (size_t)fidx[4 * g + 1] * CDIM + h * 128;
                const float* r2 = dict + (size_t)fidx[4 * g + 2] * CDIM + h * 128;
                const float* r3 = dict + (size_t)fidx[4 * g + 3] * CDIM + h * 128;
#pragma unroll
                for (int cc = 0; cc < 4; cc++) {
                    const int cl = cc * 32 + lane;
                    float4 v = make_float4(r0[cl], r1[cl], r2[cl], r3[cl]);
                    *reinterpret_cast<float4*>(smc + rt_off(cl, 4 * g)) = v;
                }
            }
            __syncthreads();
            // store: 128 c x 16 t-groups = 2048 float4 / 256 threads
#pragma unroll
            for (int j = 0; j < 8; j++) {
                const int idx = tid + j * 256;
                const int cl = idx >> 4, tg = idx & 15;
                float4 v = *reinterpret_cast<const float4*>(smc + rt_off(cl, 4 * tg));
                size_t o = ((size_t)n * CDIM + h * 128 + cl) * TDIM + tt0 + 4 * tg;
                *reinterpret_cast<float4*>(out_e + o) = v;
                *reinterpret_cast<float4*>(out_p + o) = v;
            }
        }
    }
}

// ---------------------------------------------------------------------------
extern "C" void kernel_launch(void* const* d_in, const int* in_sizes, int n_in,
                              void* d_out, int out_size) {
    const float* inputs = (const float*)d_in[0];
    const float* dict   = (const float*)d_in[1];
    float* out = (float*)d_out;

    cudaFuncSetAttribute(vq_main_kernel,
                         cudaFuncAttributeMaxDynamicSharedMemorySize, SMEM_BYTES);

    vq_hnorm_kernel<<<64, 256>>>(dict);
    vq_bfrag_kernel<<<64, 512>>>(dict);
    vq_main_kernel<<<(NBATCH * TDIM) / BT, NTHREADS, SMEM_BYTES>>>(inputs, dict, out);
}

// round 15
// speedup vs baseline: 1.1240x; 1.1240x over previous
#include <cuda_runtime.h>
#include <cuda_bf16.h>
#include <cstdint>

#define NBATCH 8
#define CDIM   256
#define TDIM   16384
#define DCODES 512
#define BT     128
#define NTHREADS 256
#define MARGIN 0.25f

// ---- smem byte layout ----
// Ah: 4 kchunks x [128 t x 128 B], XOR-swizzled, 64 KB @0
#define OFF_B     65536                 // B double buffer
#define BSTAGE    18432                 // per stage: 128 codes x 64 c (144 B rows)
#define OFF_HN    102400                // float[512]
#define OFF_FIDX  104448                // int[128]
#define OFF_BQ    104960                // float[128]
#define OFF_FLAGS 105472                // int[128]
#define OFF_FLAGN 105984                // int
#define OFF_MBAR  106000                // 4 x u64: full0 full1 empty0 empty1
#define SMEM_BYTES 106032
// overlays in Ah region (dead post-mainloop): bestv[128][16]@0, secv@8192,
// ibv@16384, isv@24576; epilogue rowsT swizzled 64 KB @0

__device__ float g_hnorm[DCODES];
__device__ __align__(256) __nv_bfloat16 g_dh16[DCODES * CDIM];

// ---------------- helpers ----------------
__device__ __forceinline__ uint32_t smem_u32(const void* p) {
    uint32_t a;
    asm("{ .reg .u64 t; cvta.to.shared.u64 t, %1; cvt.u32.u64 %0, t; }" : "=r"(a) : "l"(p));
    return a;
}
__device__ __forceinline__ void ldmx4(uint32_t r[4], uint32_t addr) {
    asm volatile("ldmatrix.sync.aligned.m8n8.x4.shared.b16 {%0,%1,%2,%3}, [%4];"
                 : "=r"(r[0]), "=r"(r[1]), "=r"(r[2]), "=r"(r[3]) : "r"(addr));
}
__device__ __forceinline__ void mma16816(float c[4], const uint32_t a[4], const uint32_t b[2]) {
    asm volatile("mma.sync.aligned.m16n8k16.row.col.f32.bf16.bf16.f32 "
                 "{%0,%1,%2,%3}, {%4,%5,%6,%7}, {%8,%9}, {%0,%1,%2,%3};"
                 : "+f"(c[0]), "+f"(c[1]), "+f"(c[2]), "+f"(c[3])
                 : "r"(a[0]), "r"(a[1]), "r"(a[2]), "r"(a[3]), "r"(b[0]), "r"(b[1]));
}
#define CPA16(dst, src) \
    asm volatile("cp.async.cg.shared.global [%0], [%1], 16;" :: "r"(dst), "l"(src) : "memory")
// .noinc: arrive counts against the init()ed expected count (one per issuing thread)
#define CPA_MBAR_ARRIVE(mb) \
    asm volatile("cp.async.mbarrier.arrive.noinc.shared.b64 [%0];" :: "r"((uint32_t)(mb)) : "memory")
#define MBARRIER_INIT(mb, c) \
    asm volatile("mbarrier.init.shared.b64 [%0], %1;" :: "r"((uint32_t)(mb)), "r"((uint32_t)(c)) : "memory")
#define MBARRIER_ARRIVE(mb) \
    asm volatile("mbarrier.arrive.shared.b64 _, [%0];" :: "r"((uint32_t)(mb)) : "memory")
#define MBARRIER_WAIT(mb, ph) do { \
    uint32_t _m = (uint32_t)(mb), _p = (uint32_t)(ph), _d; \
    asm volatile("{\n\t.reg .pred p;\n\t" \
        "mbarrier.try_wait.parity.acquire.cta.shared::cta.b64 p, [%1], %2;\n\t" \
        "selp.b32 %0, 1, 0, p;\n\t}" : "=r"(_d) : "r"(_m), "r"(_p) : "memory"); \
    if (!_d) { \
        asm volatile("{\n\t.reg .pred P1;\n\tWL_%=:\n\t" \
            "mbarrier.try_wait.parity.acquire.cta.shared::cta.b64 P1, [%0], %1, 0x989680;\n\t" \
            "@P1 bra.uni WD_%=;\n\tbra.uni WL_%=;\n\tWD_%=:\n\t}" \
            :: "r"(_m), "r"(_p) : "memory"); \
    } } while (0)

// swizzled rowsT offset (bytes): conflict-free for STS.128 along t and LDS.128 reads
__device__ __forceinline__ uint32_t rt_off(int c, int t) {
    return (uint32_t)(c * 512 + ((((t >> 2) ^ (c & 31)) << 4) | ((t & 3) << 2)));
}

// ---------------- merged prologue: hnorm + bf16-hi split ----------------
__global__ void vq_prep_kernel(const float* __restrict__ dict) {
    const int wid = threadIdx.x >> 5, lane = threadIdx.x & 31;
    const int d = blockIdx.x * 8 + wid;
    const float4* row = reinterpret_cast<const float4*>(dict + (size_t)d * CDIM);
    float4 a = row[lane * 2];
    float4 b = row[lane * 2 + 1];
    float s = a.x * a.x + a.y * a.y + a.z * a.z + a.w * a.w
            + b.x * b.x + b.y * b.y + b.z * b.z + b.w * b.w;
#pragma unroll
    for (int o = 16; o; o >>= 1) s += __shfl_xor_sync(0xffffffffu, s, o);
    if (lane == 0) g_hnorm[d] = 0.5f * s;

    __nv_bfloat162 h0 = __float22bfloat162_rn(make_float2(a.x, a.y));
    __nv_bfloat162 h1 = __float22bfloat162_rn(make_float2(a.z, a.w));
    __nv_bfloat162 h2 = __float22bfloat162_rn(make_float2(b.x, b.y));
    __nv_bfloat162 h3 = __float22bfloat162_rn(make_float2(b.z, b.w));
    uint4 v;
    v.x = *reinterpret_cast<uint32_t*>(&h0);
    v.y = *reinterpret_cast<uint32_t*>(&h1);
    v.z = *reinterpret_cast<uint32_t*>(&h2);
    v.w = *reinterpret_cast<uint32_t*>(&h3);
    reinterpret_cast<uint4*>(g_dh16 + (size_t)d * CDIM)[lane] = v;
}

// ---------------- main kernel ----------------
__global__ __launch_bounds__(NTHREADS, 2)
void vq_main_kernel(const float* __restrict__ inputs,
                    const float* __restrict__ dict,
                    float* __restrict__ out) {
    extern __shared__ float smem[];
    const uint32_t sbase = smem_u32(smem);
    char* smc = reinterpret_cast<char*>(smem);
    float* shn   = reinterpret_cast<float*>(smc + OFF_HN);
    int*   fidx  = reinterpret_cast<int*>(smc + OFF_FIDX);
    float* bq    = reinterpret_cast<float*>(smc + OFF_BQ);
    int*   flags = reinterpret_cast<int*>(smc + OFF_FLAGS);
    int*   flagn = reinterpret_cast<int*>(smc + OFF_FLAGN);
    const uint32_t fullB0 = sbase + OFF_MBAR,      fullB1 = sbase + OFF_MBAR + 8;
    const uint32_t emptB0 = sbase + OFF_MBAR + 16, emptB1 = sbase + OFF_MBAR + 24;

    const int tid = threadIdx.x;
    const int wid = tid >> 5, lane = tid & 31;
    const int wm = wid >> 2, wn = wid & 3;           // 2 x 4 warp grid
    const int n = blockIdx.x >> 7, tt0 = (blockIdx.x & 127) << 7;
    const size_t E = (size_t)NBATCH * CDIM * TDIM;

    if (tid == 0) {
        *flagn = 0;
        MBARRIER_INIT(fullB0, 256); MBARRIER_INIT(fullB1, 256);
        MBARRIER_INIT(emptB0, 8);   MBARRIER_INIT(emptB1, 8);
    }
    shn[tid] = g_hnorm[tid];
    shn[tid + 256] = g_hnorm[tid + 256];
    __syncthreads();   // mbarrier init visible before any arrive

#define STAGE_B_MB(s_, mb_) do { \
    int nc_ = (s_) >> 2, kc_ = (s_) & 3; \
    uint32_t dstb = sbase + OFF_B + ((s_) & 1) * BSTAGE; \
    const __nv_bfloat16* sH = g_dh16 + (size_t)nc_ * 128 * CDIM + kc_ * 64; \
    _Pragma("unroll") \
    for (int it = 0; it < 4; it++) { \
        int j = tid + it * 256; int d = j >> 3, u = j & 7; \
        CPA16(dstb + d * 144 + u * 16, sH + (size_t)d * CDIM + u * 8); \
    } \
    CPA_MBAR_ARRIVE(mb_); \
} while (0)

    // Prefetch B stages 0 and 1 BEFORE A-build (overlaps the A DRAM fetch)
    STAGE_B_MB(0, fullB0);
    STAGE_B_MB(1, fullB1);

    // ===== A build: direct LDG -> bf16 -> swizzled STS.128 (conflict-free) =====
    {
        const int t = tid & 127, chalf = tid >> 7;     // chalf: 0..1
        const float* xcol = inputs + (size_t)n * CDIM * TDIM + tt0 + t;
        const int x7 = t & 7;
#pragma unroll
        for (int kc = 0; kc < 4; kc++) {
#pragma unroll
            for (int q = 0; q < 4; q++) {
                const int c0 = kc * 64 + chalf * 32 + q * 8;
                float xv[8];
#pragma unroll
                for (int j = 0; j < 8; j++)
                    xv[j] = xcol[(size_t)(c0 + j) * TDIM];
                __nv_bfloat162 h;
                uint4 v;
                h = __float22bfloat162_rn(make_float2(xv[0], xv[1])); v.x = *reinterpret_cast<uint32_t*>(&h);
                h = __float22bfloat162_rn(make_float2(xv[2], xv[3])); v.y = *reinterpret_cast<uint32_t*>(&h);
                h = __float22bfloat162_rn(make_float2(xv[4], xv[5])); v.z = *reinterpret_cast<uint32_t*>(&h);
                h = __float22bfloat162_rn(make_float2(xv[6], xv[7])); v.w = *reinterpret_cast<uint32_t*>(&h);
                const int c16 = chalf * 4 + q;
                *reinterpret_cast<uint4*>(smc + kc * 16384 + t * 128 + ((c16 ^ x7) << 4)) = v;
            }
        }
    }
    __syncthreads();   // Ah complete for all warps

    // ================= mbarrier-ring mainloop (no __syncthreads) =================
    float best[8], sec[8]; int ibest[8], isec[8];
#pragma unroll
    for (int i = 0; i < 8; i++) { best[i] = -3.0e38f; sec[i] = -3.0e38f; ibest[i] = 0x3fffffff; isec[i] = 0x3fffffff; }

    const uint32_t aBase = sbase + (uint32_t)(wm * 8192 + (lane & 15) * 128);
    uint32_t aOff[4];
#pragma unroll
    for (int ks = 0; ks < 4; ks++)
        aOff[ks] = (uint32_t)(((ks * 2 + (lane >> 4)) ^ (lane & 7)) << 4);

    const uint32_t bRow  = (uint32_t)((wn * 32 + ((lane >> 4) & 1) * 8 + (lane & 7)) * 144 +
                                      ((lane >> 3) & 1) * 16);

    float acc[4][4][4];
    for (int s = 0; s < 16; s++) {
        const int nc = s >> 2, kc = s & 3;
        const int buf = s & 1, ph = (s >> 1) & 1;
        const uint32_t fullB = buf ? fullB1 : fullB0;
        const uint32_t emptB = buf ? emptB1 : emptB0;

        if (kc == 0) {
#pragma unroll
            for (int mt = 0; mt < 4; mt++)
#pragma unroll
                for (int nt = 0; nt < 4; nt++)
#pragma unroll
                    for (int e = 0; e < 4; e++) acc[mt][nt][e] = 0.f;
        }

        MBARRIER_WAIT(fullB, ph);   // B stage data landed

        const uint32_t aH = aBase + kc * 16384;
        const uint32_t bH = sbase + OFF_B + buf * BSTAGE + bRow;

#pragma unroll
        for (int ks = 0; ks < 4; ks++) {
            const uint32_t koff = ks * 32;
            uint32_t ah[4][4], bh[4][2];
#pragma unroll
            for (int mt = 0; mt < 4; mt++) ldmx4(ah[mt], aH + mt * 2048 + aOff[ks]);
            {
                uint32_t tp[4];
                ldmx4(tp, bH + koff);        bh[0][0]=tp[0]; bh[0][1]=tp[1]; bh[1][0]=tp[2]; bh[1][1]=tp[3];
                ldmx4(tp, bH + 2304 + koff); bh[2][0]=tp[0]; bh[2][1]=tp[1]; bh[3][0]=tp[2]; bh[3][1]=tp[3];
            }
#pragma unroll
            for (int mt = 0; mt < 4; mt++)
#pragma unroll
                for (int nt = 0; nt < 4; nt++) mma16816(acc[mt][nt], ah[mt], bh[nt]);
        }

        if (lane == 0) MBARRIER_ARRIVE(emptB);   // this warp done reading buf

        if (s + 2 < 16) {
            MBARRIER_WAIT(emptB, ph);            // all warps done with buf
            STAGE_B_MB(s + 2, fullB);            // refill buf for stage s+2
        }

        if (kc == 3) {
            const int dbase = nc * 128 + wn * 32 + (lane & 3) * 2;
#pragma unroll
            for (int mt = 0; mt < 4; mt++) {
#pragma unroll
                for (int rh = 0; rh < 2; rh++) {
                    const int li = mt * 2 + rh;
                    float b_ = best[li], s_ = sec[li]; int bi_ = ibest[li], si_ = isec[li];
#pragma unroll
                    for (int nt = 0; nt < 4; nt++) {
#pragma unroll
                        for (int cc = 0; cc < 2; cc++) {
                            const int d = dbase + nt * 8 + cc;
                            float v = acc[mt][nt][rh * 2 + cc] - shn[d];
                            if (v > b_)      { s_ = b_; si_ = bi_; b_ = v; bi_ = d; }
                            else if (v > s_) { s_ = v;  si_ = d; }
                        }
                    }
                    best[li] = b_; sec[li] = s_; ibest[li] = bi_; isec[li] = si_;
                }
            }
        }
    }
    __syncthreads();   // Ah dead; overlay tables

    // ================= per-group top-2 publish =================
    float* bestv = smem;                               // [128][16]
    float* secv  = smem + 2048;
    int*   ibv   = reinterpret_cast<int*>(smem + 4096);
    int*   isv   = reinterpret_cast<int*>(smem + 6144);
    {
        const int slot = wn * 4 + (lane & 3);
#pragma unroll
        for (int mt = 0; mt < 4; mt++)
#pragma unroll
            for (int rh = 0; rh < 2; rh++) {
                const int li = mt * 2 + rh;
                const int t = wm * 64 + mt * 16 + (lane >> 2) + rh * 8;
                bestv[t * 16 + slot] = best[li];
                secv [t * 16 + slot] = sec[li];
                ibv  [t * 16 + slot] = ibest[li];
                isv  [t * 16 + slot] = isec[li];
            }
    }
    __syncthreads();

    // ================= approx argmax + candidate flagging =================
    if (tid < BT) {
        float B = -3.0e38f; int I = 0x3fffffff;
#pragma unroll 4
        for (int q = 0; q < 16; q++) {
            float b = bestv[tid * 16 + q];
            int   i = ibv[tid * 16 + q];
            if (b > B || (b == B && i < I)) { B = b; I = i; }
        }
        int ncand = 0;
#pragma unroll 4
        for (int k = 0; k < 32; k++) {
            float s2 = (k < 16) ? bestv[tid * 16 + k] : secv[tid * 16 + (k - 16)];
            int   i2 = (k < 16) ? ibv[tid * 16 + k]   : isv[tid * 16 + (k - 16)];
            if (s2 > B - MARGIN && i2 != I) ncand++;
        }
        fidx[tid] = I; bq[tid] = B;
        if (ncand) { int p = atomicAdd(flagn, 1); flags[p] = tid; }
    }
    __syncthreads();

    // ================= exact fp32 rescore of ALL in-margin candidates =================
    {
        const int nf = *flagn;
        for (int e = wid; e < nf; e += 8) {
            const int q = flags[e];
            const float B = bq[q];
            const float* xp = inputs + ((size_t)n * CDIM) * TDIM + tt0 + q;
            float xr[8];
#pragma unroll
            for (int j = 0; j < 8; j++) xr[j] = xp[(size_t)(lane + 32 * j) * TDIM];
            float bestE = -3.0e38f; int bestI = 0x3fffffff;
            for (int k = 0; k < 32; k++) {
                float s2 = (k < 16) ? bestv[q * 16 + k] : secv[q * 16 + (k - 16)];
                int   i2 = (k < 16) ? ibv[q * 16 + k]   : isv[q * 16 + (k - 16)];
                if (s2 > B - MARGIN) {
                    const float* drow = dict + (size_t)i2 * CDIM;
                    float p = 0.f;
#pragma unroll
                    for (int j = 0; j < 8; j++) p += xr[j] * drow[lane + 32 * j];
#pragma unroll
                    for (int o = 16; o; o >>= 1) p += __shfl_xor_sync(0xffffffffu, p, o);
                    float c = p - shn[i2];
                    if (c > bestE || (c == bestE && i2 < bestI)) { bestE = c; bestI = i2; }
                }
            }
            if (lane == 0) fidx[q] = bestI;
        }
    }
    __syncthreads();

    if (tid < BT)
        out[2 * E + (size_t)n * TDIM + tt0 + tid] = (float)fidx[tid];

    // ================= swizzled conflict-free epilogue: 2 c-halves =================
    {
        float* out_e = out;
        float* out_p = out + E;
        for (int h = 0; h < 2; h++) {
            __syncthreads();   // previous half reads done / rescore tables dead
#pragma unroll
            for (int g4 = 0; g4 < 4; g4++) {
                const int g = wid + 8 * g4;
                const float* r0 = dict + (size_t)fidx[4 * g    ] * CDIM + h * 128;
                const float* r1 = dict + (size_t)fidx[4 * g + 1] * CDIM + h * 128;
                const float* r2 = dict + (size_t)fidx[4 * g + 2] * CDIM + h * 128;
                const float* r3 = dict + (size_t)fidx[4 * g + 3] * CDIM + h * 128;
#pragma unroll
                for (int cc = 0; cc < 4; cc++) {
                    const int cl = cc * 32 + lane;
                    float4 v = make_float4(r0[cl], r1[cl], r2[cl], r3[cl]);
                    *reinterpret_cast<float4*>(smc + rt_off(cl, 4 * g)) = v;
                }
            }
            __syncthreads();
#pragma unroll
            for (int j = 0; j < 16; j++) {
                const int cl = wid + 8 * j;
                float4 v = *reinterpret_cast<const float4*>(smc + rt_off(cl, 4 * lane));
                size_t o = ((size_t)n * CDIM + h * 128 + cl) * TDIM + tt0 + 4 * lane;
                *reinterpret_cast<float4*>(out_e + o) = v;
                *reinterpret_cast<float4*>(out_p + o) = v;
            }
        }
    }
}

// ---------------------------------------------------------------------------
extern "C" void kernel_launch(void* const* d_in, const int* in_sizes, int n_in,
                              void* d_out, int out_size) {
    const float* inputs = (const float*)d_in[0];
    const float* dict   = (const float*)d_in[1];
    float* out = (float*)d_out;

    cudaFuncSetAttribute(vq_main_kernel,
                         cudaFuncAttributeMaxDynamicSharedMemorySize, SMEM_BYTES);

    vq_prep_kernel<<<64, 256>>>(dict);
    vq_main_kernel<<<(NBATCH * TDIM) / BT, NTHREADS, SMEM_BYTES>>>(inputs, dict, out);
}